// round 14
// baseline (speedup 1.0000x reference)
#include <cuda_runtime.h>
#include <cuda_bf16.h>
#include <math.h>
#include <stdint.h>

#define NN    100000
#define KNB   20
#define DKF   384
#define UPAD  400     // padded per-head u stride (float4-aligned)
#define NNODES 200000

// ================= device scratch =================
__device__ float g_comb[(size_t)NNODES * 128];   // node_feat + memory (precomputed)
__device__ float g_u[(size_t)NN * 800];          // u padded: [h0 c0..384 pad][h1 c0..384 pad]
__device__ uint4 g_qh[(size_t)NN * 16];          // q hi  (N x 128 bf16)
__device__ uint4 g_ql[(size_t)NN * 16];          // q lo
__device__ uint4 g_mh[(size_t)NN * 96];          // mixed hi (N x 768 bf16)
__device__ uint4 g_ml[(size_t)NN * 96];          // mixed lo
__device__ uint4 g_h1h[(size_t)NN * 16];         // h1 hi (N x 128 bf16)
__device__ uint4 g_h1l[(size_t)NN * 16];         // h1 lo
__device__ uint4 g_Muh[14336], g_Mul[14336];     // Mu 800(pad 896) x 128 bf16
__device__ uint4 g_Bfh[14336], g_Bfl[14336];     // Bf 128 x 896 bf16
__device__ uint4 g_W2h[2048], g_W2l[2048];       // W2 128 x 128 bf16
__device__ float g_du[896];
__device__ float g_Pt[256 * 128];
__device__ float g_cvec[128];
__device__ unsigned char g_flags[NN];
__device__ int   g_mask_is_byte;

// ================= PTX helpers (baseline features only) =================
__device__ __forceinline__ uint32_t smem_u32(const void* p) {
    uint32_t r;
    asm("{ .reg .u64 t; cvta.to.shared.u64 t, %1; cvt.u32.u64 %0, t; }" : "=r"(r) : "l"(p));
    return r;
}
__device__ __forceinline__ void ldm_x4(uint32_t* r, uint32_t addr) {
    asm volatile("ldmatrix.sync.aligned.m8n8.x4.shared.b16 {%0,%1,%2,%3}, [%4];"
                 : "=r"(r[0]), "=r"(r[1]), "=r"(r[2]), "=r"(r[3]) : "r"(addr));
}
__device__ __forceinline__ void ldm_x2(uint32_t* r, uint32_t addr) {
    asm volatile("ldmatrix.sync.aligned.m8n8.x2.shared.b16 {%0,%1}, [%2];"
                 : "=r"(r[0]), "=r"(r[1]) : "r"(addr));
}
__device__ __forceinline__ void mma16816(float* c, const uint32_t* a, const uint32_t* b) {
    asm volatile("mma.sync.aligned.m16n8k16.row.col.f32.bf16.bf16.f32 "
        "{%0,%1,%2,%3}, {%4,%5,%6,%7}, {%8,%9}, {%0,%1,%2,%3};"
        : "+f"(c[0]), "+f"(c[1]), "+f"(c[2]), "+f"(c[3])
        : "r"(a[0]), "r"(a[1]), "r"(a[2]), "r"(a[3]), "r"(b[0]), "r"(b[1]));
}
__device__ __forceinline__ void cpasync16(uint32_t dst, const void* src, uint32_t srcsize) {
    asm volatile("cp.async.cg.shared.global [%0], [%1], 16, %2;"
                 :: "r"(dst), "l"(src), "r"(srcsize));
}
__device__ __forceinline__ void cpasync16(uint32_t dst, const void* src) {
    asm volatile("cp.async.cg.shared.global [%0], [%1], 16;" :: "r"(dst), "l"(src));
}
__device__ __forceinline__ int mget(const void* m, int i, int isbyte) {
    return isbyte ? (((const unsigned char*)m)[i] != 0) : (((const int*)m)[i] != 0);
}

// ================= setup / compose =================
__device__ __forceinline__ void split_store(__nv_bfloat16* ph, __nv_bfloat16* pl, size_t i, float v) {
    __nv_bfloat16 h = __float2bfloat16(v);
    ph[i] = h;
    pl[i] = __float2bfloat16(v - __bfloat162float(h));
}

// composeU: Mu + du with qhconst folded in; PADDED rows (800 = 2 x 400).
__global__ void k_composeU(const float* __restrict__ Wk, const float* __restrict__ bk,
                           const float* __restrict__ Wq, const float* __restrict__ bq,
                           const float* __restrict__ time_b,
                           __nv_bfloat16* __restrict__ Mh, __nv_bfloat16* __restrict__ Ml,
                           float* __restrict__ du)
{
    int hc = blockIdx.x;          // 0..799
    int h = hc / UPAD, c = hc % UPAD;
    int e = threadIdx.x;          // 0..127
    __shared__ float krow[128];
    __shared__ float cb[128];
    __shared__ float red[128];
    cb[e] = cosf(time_b[e]);
    krow[e] = (c < 384) ? Wk[(size_t)(h * 128 + e) * 384 + c]
            : ((c == 384) ? bk[h * 128 + e] : 0.f);
    __syncthreads();
    float acc1 = 0.f, acc2 = 0.f;
    #pragma unroll 4
    for (int d = 0; d < 128; d++) {
        const float* row = Wq + (size_t)(h * 128 + d) * 256;
        float kd = krow[d];
        acc1 += kd * row[e];
        acc2 += kd * row[128 + e];
    }
    split_store(Mh, Ml, (size_t)hc * 128 + e, acc1);
    red[e] = acc2 * cb[e] + krow[e] * bq[h * 128 + e];
    __syncthreads();
    for (int off = 64; off; off >>= 1) {
        if (e < off) red[e] += red[e + off];
        __syncthreads();
    }
    if (e == 0) du[hc] = red[0];
}

// k_prep: comb (all nodes) + q gather/split + mask-layout probe, one launch.
__global__ void k_prep(const int* __restrict__ idx,
                       const float* __restrict__ nf, const float* __restrict__ mem,
                       float* __restrict__ comb,
                       __nv_bfloat16* __restrict__ qh, __nv_bfloat16* __restrict__ ql,
                       const unsigned char* __restrict__ mask,
                       int n, int nbComb, int nbGather)
{
    int b = blockIdx.x;
    if (b < nbComb) {
        size_t i = (size_t)b * 256 + threadIdx.x;
        if (i < (size_t)NNODES * 32) {
            float4 a = ((const float4*)nf)[i];
            float4 m = ((const float4*)mem)[i];
            ((float4*)comb)[i] = make_float4(a.x + m.x, a.y + m.y, a.z + m.z, a.w + m.w);
        }
    } else if (b < nbComb + nbGather) {
        int i = (b - nbComb) * 256 + threadIdx.x;
        if (i < n * 32) {
            int node = i >> 5, c4 = i & 31;
            int src = idx[node];
            float4 a = ((const float4*)nf)[(size_t)src * 32 + c4];
            float4 m = ((const float4*)mem)[(size_t)src * 32 + c4];
            float v[4] = { a.x + m.x, a.y + m.y, a.z + m.z, a.w + m.w };
            size_t base = (size_t)i * 4;
            #pragma unroll
            for (int j = 0; j < 4; j++) split_store(qh, ql, base + j, v[j]);
        }
    } else {
        int any = 0;
        for (int i = threadIdx.x; i < 8192; i += 256)
            if ((i & 3) != 0 && mask[i] != 0) any = 1;
        int r = __syncthreads_or(any);
        if (threadIdx.x == 0) g_mask_is_byte = r ? 1 : 0;
    }
}

__global__ void k_composeP(const float* __restrict__ W1, const float* __restrict__ Wo,
                           const float* __restrict__ bv, const float* __restrict__ bo,
                           float* __restrict__ Pt, float* __restrict__ cvec)
{
    int r = blockIdx.x;           // 0..127
    int a = threadIdx.x;          // 0..255
    __shared__ float w1row[256];
    __shared__ float red[256];
    w1row[a] = W1[(size_t)r * 384 + a];
    __syncthreads();
    float acc = 0.f;
    #pragma unroll 8
    for (int s = 0; s < 256; s++) acc += w1row[s] * Wo[(size_t)s * 256 + a];
    Pt[(size_t)a * 128 + r] = acc;
    red[a] = acc * bv[a] + w1row[a] * bo[a];
    __syncthreads();
    for (int off = 128; off; off >>= 1) {
        if (a < off) red[a] += red[a + off];
        __syncthreads();
    }
    if (a == 0) cvec[r] = red[0];
}

__global__ void k_composeC(const float* __restrict__ Pt, const float* __restrict__ Wv,
                           const float* __restrict__ W1,
                           __nv_bfloat16* __restrict__ Bh, __nv_bfloat16* __restrict__ Bl)
{
    int j = blockIdx.x;           // 0..895
    int r = threadIdx.x;          // 0..127
    if (j >= 768) {
        split_store(Bh, Bl, (size_t)r * 896 + j, W1[(size_t)r * 384 + 256 + (j - 768)]);
        return;
    }
    int h = j / 384, c = j % 384;
    __shared__ float wvcol[128];
    wvcol[r] = Wv[(size_t)(h * 128 + r) * 384 + c];
    __syncthreads();
    float acc = 0.f;
    #pragma unroll 8
    for (int d = 0; d < 128; d++)
        acc += Pt[(size_t)(h * 128 + d) * 128 + r] * wvcol[d];
    split_store(Bh, Bl, (size_t)r * 896 + j, acc);
}

__global__ void k_splitW2(const float* __restrict__ W2,
                          __nv_bfloat16* __restrict__ wh, __nv_bfloat16* __restrict__ wl)
{
    int i = blockIdx.x * 256 + threadIdx.x;
    if (i < 128 * 128) split_store(wh, wl, i, W2[i]);
}

// ================= HMMA GEMM (cp.async double-buffered, 2 CTAs/SM) ===========
#define LDS_STRIDE 40                 // bf16 elems; 80B rows, ldmatrix conflict-free
#define TILE_B     (128 * LDS_STRIDE * 2)   // 10240 bytes per tile
#define STAGE_B    (4 * TILE_B)             // AsH AsL BsH BsL
#define SMEM_GEMM  (2 * STAGE_B)            // 81920

template<int EPI>
__global__ __launch_bounds__(256, 2)
void mma_gemm(const __nv_bfloat16* __restrict__ Ah, const __nv_bfloat16* __restrict__ Al, int lda,
              const __nv_bfloat16* __restrict__ A2h, const __nv_bfloat16* __restrict__ A2l, int lda2, int ksplit,
              const __nv_bfloat16* __restrict__ Bh, const __nv_bfloat16* __restrict__ Bl, int ldb,
              int ktiles, int Rtot,
              const float* __restrict__ bias, const float* __restrict__ bias2,
              const unsigned char* __restrict__ flags,
              float* __restrict__ OutF, int ldc,
              __nv_bfloat16* __restrict__ OutH, __nv_bfloat16* __restrict__ OutL, int Ntot)
{
    extern __shared__ char dsm[];
    const uint32_t sb = smem_u32(dsm);

    const int tid = threadIdx.x;
    const int lane = tid & 31, wid = tid >> 5;
    const int wm = wid >> 2, wn = wid & 3;      // 2 x 4 warp grid
    const int m0 = blockIdx.x * 128;
    const int r0 = blockIdx.y * 128;

    int vrows = Ntot - m0;
    if (vrows > 128) vrows = 128;
    if (vrows < 0) vrows = 0;

    float acc[4][4][4];
    #pragma unroll
    for (int a = 0; a < 4; a++)
        #pragma unroll
        for (int b = 0; b < 4; b++)
            #pragma unroll
            for (int c = 0; c < 4; c++) acc[a][b][c] = 0.f;

    const int lrow = tid >> 2;                 // 0..63 (+64 on 2nd pass)
    const int lc8 = (tid & 3) * 8;             // bf16 col within 32

    auto issue_stage = [&](int kt) {
        uint32_t base = sb + (kt & 1) * STAGE_B;
        const __nv_bfloat16 *sh, *sl; int st, k0;
        if (kt < ksplit) { sh = Ah;  sl = Al;  st = lda;  k0 = kt * 32; }
        else             { sh = A2h; sl = A2l; st = lda2; k0 = (kt - ksplit) * 32; }
        #pragma unroll
        for (int i = 0; i < 2; i++) {
            int row = lrow + i * 64;
            int srow = (row < vrows) ? row : 0;
            uint32_t sz = (row < vrows) ? 16u : 0u;
            uint32_t doff = row * (LDS_STRIDE * 2) + lc8 * 2;
            cpasync16(base + doff,
                      sh + (size_t)(m0 + srow) * st + k0 + lc8, sz);
            cpasync16(base + TILE_B + doff,
                      sl + (size_t)(m0 + srow) * st + k0 + lc8, sz);
            cpasync16(base + 2 * TILE_B + doff,
                      Bh + (size_t)(r0 + row) * ldb + kt * 32 + lc8);
            cpasync16(base + 3 * TILE_B + doff,
                      Bl + (size_t)(r0 + row) * ldb + kt * 32 + lc8);
        }
        asm volatile("cp.async.commit_group;" ::: "memory");
    };

    const int arow = wm * 64 + (lane & 15);
    const int acolsel = ((lane >> 4) & 1) * 8;
    const int l16 = lane & 15;
    const int brow = wn * 32 + (l16 & 7);
    const int bcolsel = ((l16 >> 3) & 1) * 8;

    issue_stage(0);

    for (int kt = 0; kt < ktiles; kt++) {
        if (kt + 1 < ktiles) {
            issue_stage(kt + 1);
            asm volatile("cp.async.wait_group 1;" ::: "memory");
        } else {
            asm volatile("cp.async.wait_group 0;" ::: "memory");
        }
        __syncthreads();

        const uint32_t cb = sb + (kt & 1) * STAGE_B;
        const uint32_t sAH = cb, sAL = cb + TILE_B;
        const uint32_t sBH = cb + 2 * TILE_B, sBL = cb + 3 * TILE_B;

        #pragma unroll
        for (int ks = 0; ks < 2; ks++) {
            const int acol = ks * 16 + acolsel;
            const int bcol = ks * 16 + bcolsel;
            uint32_t af[4][4], bhf[4][2], blf[4][2];
            #pragma unroll
            for (int mi = 0; mi < 4; mi++)
                ldm_x4(af[mi], sAH + (uint32_t)(((arow + mi * 16) * LDS_STRIDE + acol) * 2));
            #pragma unroll
            for (int ni = 0; ni < 4; ni++) {
                ldm_x2(bhf[ni], sBH + (uint32_t)(((brow + ni * 8) * LDS_STRIDE + bcol) * 2));
                ldm_x2(blf[ni], sBL + (uint32_t)(((brow + ni * 8) * LDS_STRIDE + bcol) * 2));
            }
            #pragma unroll
            for (int mi = 0; mi < 4; mi++)
                #pragma unroll
                for (int ni = 0; ni < 4; ni++) {
                    mma16816(acc[mi][ni], af[mi], bhf[ni]);   // Ah*Bh
                    mma16816(acc[mi][ni], af[mi], blf[ni]);   // Ah*Bl
                }
            #pragma unroll
            for (int mi = 0; mi < 4; mi++)
                ldm_x4(af[mi], sAL + (uint32_t)(((arow + mi * 16) * LDS_STRIDE + acol) * 2));
            #pragma unroll
            for (int mi = 0; mi < 4; mi++)
                #pragma unroll
                for (int ni = 0; ni < 4; ni++)
                    mma16816(acc[mi][ni], af[mi], bhf[ni]);   // Al*Bh
        }
        __syncthreads();
    }

    // ---- epilogue ----
    #pragma unroll
    for (int mi = 0; mi < 4; mi++) {
        int nrow0 = m0 + wm * 64 + mi * 16 + (lane >> 2);
        #pragma unroll
        for (int half = 0; half < 2; half++) {
            int n = nrow0 + half * 8;
            if (n >= Ntot) continue;
            bool fl = false;
            if (EPI == 1) fl = (flags[n] != 0);
            #pragma unroll
            for (int ni = 0; ni < 4; ni++) {
                int r = r0 + wn * 32 + ni * 8 + (lane & 3) * 2;
                float v0 = acc[mi][ni][half * 2 + 0];
                float v1 = acc[mi][ni][half * 2 + 1];
                if (EPI == 0) {
                    if (r < Rtot)     OutF[(size_t)n * ldc + r]     = v0 + bias[r];
                    if (r + 1 < Rtot) OutF[(size_t)n * ldc + r + 1] = v1 + bias[r + 1];
                } else if (EPI == 1) {
                    v0 += bias[r]     + (fl ? 0.f : bias2[r]);
                    v1 += bias[r + 1] + (fl ? 0.f : bias2[r + 1]);
                    v0 = fmaxf(v0, 0.f);
                    v1 = fmaxf(v1, 0.f);
                    __nv_bfloat16 h0 = __float2bfloat16(v0), h1 = __float2bfloat16(v1);
                    *(__nv_bfloat162*)(OutH + (size_t)n * 128 + r) = __halves2bfloat162(h0, h1);
                    __nv_bfloat16 l0 = __float2bfloat16(v0 - __bfloat162float(h0));
                    __nv_bfloat16 l1 = __float2bfloat16(v1 - __bfloat162float(h1));
                    *(__nv_bfloat162*)(OutL + (size_t)n * 128 + r) = __halves2bfloat162(l0, l1);
                } else {
                    OutF[(size_t)n * ldc + r]     = v0 + bias[r];
                    OutF[(size_t)n * ldc + r + 1] = v1 + bias[r + 1];
                }
            }
        }
    }
}

// ================= fused per-node edge kernel =================
// Valid-slot compaction: all phases iterate only over the V valid rows.
__global__ __launch_bounds__(256)
void k_edge(const int* __restrict__ neighbors, const float* __restrict__ t,
            const float* __restrict__ e_t, const int* __restrict__ e_id,
            const void* __restrict__ mask,
            const float* __restrict__ comb,
            const float* __restrict__ event_feat,
            const float* __restrict__ time_w, const float* __restrict__ time_b,
            const float* __restrict__ u,
            __nv_bfloat16* __restrict__ mixh, __nv_bfloat16* __restrict__ mixl,
            unsigned char* __restrict__ flags, int Ntot)
{
    int n = blockIdx.x;
    if (n >= Ntot) return;
    int tid = threadIdx.x;
    int lane = tid & 31, warp = tid >> 5;
    const int isb = g_mask_is_byte;

    __shared__ float kvc[KNB][DKF];     // rows indexed by compacted v
    __shared__ float tw[128], tb[128];
    __shared__ float attn[2][KNB];      // compacted
    __shared__ float sc[2][KNB];        // compacted
    __shared__ int s_nb[KNB], s_eid[KNB], s_mk[KNB];   // original slot order
    __shared__ float s_dt[KNB];
    __shared__ int s_vk[KNB];           // compacted -> original slot index
    __shared__ int s_nonb, s_V;

    // u -> regs for score warps 0-3 (issued first; independent of everything)
    const float* ubase = u + (size_t)n * 800;
    float4 u0[3], u1[3];
    float ub0 = 0.f, ub1 = 0.f;
    if (warp < 4) {
        #pragma unroll
        for (int i = 0; i < 3; i++) {
            u0[i] = *(const float4*)(ubase + lane * 4 + 128 * i);
            u1[i] = *(const float4*)(ubase + UPAD + lane * 4 + 128 * i);
        }
        ub0 = ubase[384]; ub1 = ubase[UPAD + 384];
    }

    // constants loaded by warps 4-7; metadata by warp 0 lanes <20
    if (tid >= 128) { tw[tid - 128] = time_w[tid - 128]; tb[tid - 128] = time_b[tid - 128]; }
    if (tid < KNB) {
        s_nb[tid]  = neighbors[n * KNB + tid];
        s_eid[tid] = e_id[n * KNB + tid];
        s_mk[tid]  = mget(mask, n * KNB + tid, isb);
        s_dt[tid]  = t[n] - e_t[n * KNB + tid];
    }
    __syncthreads();

    // valid-slot compaction (warp 0)
    if (warp == 0) {
        int mk = (lane < KNB) ? s_mk[lane] : 0;
        unsigned bal = __ballot_sync(0xffffffffu, mk != 0);
        int nonb = (bal == 0);
        int validb = (lane < KNB) && (mk | nonb);
        unsigned vb = __ballot_sync(0xffffffffu, validb);
        if (validb) {
            int pos = __popc(vb & ((1u << lane) - 1));
            s_vk[pos] = lane;
        }
        if (lane == 0) { s_nonb = nonb; s_V = __popc(vb); }
    }
    __syncthreads();
    const int nonb = s_nonb;
    const int V = s_V;
    const uint32_t kvb = smem_u32(kvc);

    // phase B: gathers for VALID rows only (cp.async; comb gated by mk)
    for (int i = tid; i < V * 32; i += 256) {
        int v = i >> 5, c4 = i & 31;
        int k = s_vk[v];
        int mk = s_mk[k];
        cpasync16(kvb + (uint32_t)(v * DKF + c4 * 4) * 4,
                  comb + (size_t)s_nb[k] * 128 + c4 * 4, mk ? 16u : 0u);
        cpasync16(kvb + (uint32_t)(v * DKF + 256 + c4 * 4) * 4,
                  event_feat + (size_t)s_eid[k] * 128 + c4 * 4);
    }
    asm volatile("cp.async.commit_group;" ::: "memory");

    // phase C: time encode for VALID rows while gathers are in flight
    for (int i = tid; i < V * 32; i += 256) {
        int v = i >> 5, c4 = i & 31;
        float dt = s_dt[s_vk[v]];
        int j = c4 * 4;
        float4 o;
        o.x = __cosf(__fadd_rn(__fmul_rn(dt, tw[j + 0]), tb[j + 0]));
        o.y = __cosf(__fadd_rn(__fmul_rn(dt, tw[j + 1]), tb[j + 1]));
        o.z = __cosf(__fadd_rn(__fmul_rn(dt, tw[j + 2]), tb[j + 2]));
        o.w = __cosf(__fadd_rn(__fmul_rn(dt, tw[j + 3]), tb[j + 3]));
        *(float4*)&kvc[v][128 + j] = o;
    }
    asm volatile("cp.async.wait_group 0;" ::: "memory");
    __syncthreads();

    // scores over compacted rows: 4 warps; one kvc float4 read feeds BOTH heads
    if (warp < 4) {
        for (int v = warp; v < V; v += 4) {
            float a0 = 0.f, a1 = 0.f;
            #pragma unroll
            for (int i = 0; i < 3; i++) {
                float4 w = *(const float4*)&kvc[v][lane * 4 + 128 * i];
                a0 += u0[i].x * w.x + u0[i].y * w.y + u0[i].z * w.z + u0[i].w * w.w;
                a1 += u1[i].x * w.x + u1[i].y * w.y + u1[i].z * w.z + u1[i].w * w.w;
            }
            #pragma unroll
            for (int off = 16; off; off >>= 1) {
                a0 += __shfl_down_sync(0xffffffffu, a0, off);
                a1 += __shfl_down_sync(0xffffffffu, a1, off);
            }
            if (lane == 0) {
                sc[0][v] = (a0 + ub0) * 0.08838834764831845f;
                sc[1][v] = (a1 + ub1) * 0.08838834764831845f;
            }
        }
    }
    __syncthreads();

    // softmax over compacted rows (warps 0,1)
    if (warp < 2) {
        int h = warp;
        float s = (lane < V) ? sc[h][lane] : -INFINITY;
        float m = s;
        #pragma unroll
        for (int off = 16; off; off >>= 1) m = fmaxf(m, __shfl_xor_sync(0xffffffffu, m, off));
        float e = (lane < V) ? __expf(s - m) : 0.f;
        float sum = e;
        #pragma unroll
        for (int off = 16; off; off >>= 1) sum += __shfl_xor_sync(0xffffffffu, sum, off);
        if (lane < V) attn[h][lane] = e / sum;
    }
    __syncthreads();

    // mix over compacted rows: one float2 kvc read feeds BOTH heads
    float gate = nonb ? 0.f : 1.f;
    if (tid < 192) {
        int j = tid * 2;
        float a00 = 0.f, a01 = 0.f, a10 = 0.f, a11 = 0.f;
        for (int v = 0; v < V; v++) {
            float2 w = *(const float2*)&kvc[v][j];
            float w0 = attn[0][v], w1 = attn[1][v];
            a00 += w0 * w.x; a01 += w0 * w.y;
            a10 += w1 * w.x; a11 += w1 * w.y;
        }
        a00 *= gate; a01 *= gate; a10 *= gate; a11 *= gate;
        __nv_bfloat16 h00 = __float2bfloat16(a00), h01 = __float2bfloat16(a01);
        __nv_bfloat16 h10 = __float2bfloat16(a10), h11 = __float2bfloat16(a11);
        *(__nv_bfloat162*)(mixh + (size_t)n * 768 + j)       = __halves2bfloat162(h00, h01);
        *(__nv_bfloat162*)(mixh + (size_t)n * 768 + 384 + j) = __halves2bfloat162(h10, h11);
        __nv_bfloat16 l00 = __float2bfloat16(a00 - __bfloat162float(h00));
        __nv_bfloat16 l01 = __float2bfloat16(a01 - __bfloat162float(h01));
        __nv_bfloat16 l10 = __float2bfloat16(a10 - __bfloat162float(h10));
        __nv_bfloat16 l11 = __float2bfloat16(a11 - __bfloat162float(h11));
        *(__nv_bfloat162*)(mixl + (size_t)n * 768 + j)       = __halves2bfloat162(l00, l01);
        *(__nv_bfloat162*)(mixl + (size_t)n * 768 + 384 + j) = __halves2bfloat162(l10, l11);
    }
    if (tid == 0) flags[n] = (unsigned char)nonb;
}

// ================= launch =================
extern "C" void kernel_launch(void* const* d_in, const int* in_sizes, int n_in,
                              void* d_out, int out_size)
{
    const int*   idx        = (const int*)d_in[0];
    const float* t          = (const float*)d_in[1];
    const int*   neighbors  = (const int*)d_in[2];
    const float* e_t        = (const float*)d_in[3];
    const int*   e_id       = (const int*)d_in[4];
    const void*  mask       = d_in[5];
    const float* node_feat  = (const float*)d_in[6];
    const float* memory     = (const float*)d_in[7];
    const float* event_feat = (const float*)d_in[8];
    const float* time_w     = (const float*)d_in[9];
    const float* time_b     = (const float*)d_in[10];
    const float* Wq = (const float*)d_in[11];
    const float* bq = (const float*)d_in[12];
    const float* Wk = (const float*)d_in[13];
    const float* bk = (const float*)d_in[14];
    const float* Wv = (const float*)d_in[15];
    const float* bv = (const float*)d_in[16];
    const float* Wo = (const float*)d_in[17];
    const float* bo = (const float*)d_in[18];
    const float* W1 = (const float*)d_in[19];
    const float* b1 = (const float*)d_in[20];
    const float* W2 = (const float*)d_in[21];
    const float* b2 = (const float*)d_in[22];
    float* out = (float*)d_out;

    int N = in_sizes[0];
    if (N > NN) N = NN;

    float *u, *du, *Pt, *cvec, *comb;
    __nv_bfloat16 *qh, *ql, *mh, *ml, *h1h, *h1l, *Muh, *Mul, *Bfh, *Bfl, *W2h, *W2l;
    unsigned char* flags;
    cudaGetSymbolAddress((void**)&u, g_u);
    cudaGetSymbolAddress((void**)&du, g_du);
    cudaGetSymbolAddress((void**)&Pt, g_Pt);
    cudaGetSymbolAddress((void**)&cvec, g_cvec);
    cudaGetSymbolAddress((void**)&comb, g_comb);
    cudaGetSymbolAddress((void**)&qh, g_qh);
    cudaGetSymbolAddress((void**)&ql, g_ql);
    cudaGetSymbolAddress((void**)&mh, g_mh);
    cudaGetSymbolAddress((void**)&ml, g_ml);
    cudaGetSymbolAddress((void**)&h1h, g_h1h);
    cudaGetSymbolAddress((void**)&h1l, g_h1l);
    cudaGetSymbolAddress((void**)&Muh, g_Muh);
    cudaGetSymbolAddress((void**)&Mul, g_Mul);
    cudaGetSymbolAddress((void**)&Bfh, g_Bfh);
    cudaGetSymbolAddress((void**)&Bfl, g_Bfl);
    cudaGetSymbolAddress((void**)&W2h, g_W2h);
    cudaGetSymbolAddress((void**)&W2l, g_W2l);
    cudaGetSymbolAddress((void**)&flags, g_flags);

    cudaFuncSetAttribute(mma_gemm<0>, cudaFuncAttributeMaxDynamicSharedMemorySize, SMEM_GEMM);
    cudaFuncSetAttribute(mma_gemm<1>, cudaFuncAttributeMaxDynamicSharedMemorySize, SMEM_GEMM);
    cudaFuncSetAttribute(mma_gemm<2>, cudaFuncAttributeMaxDynamicSharedMemorySize, SMEM_GEMM);

    int mtiles = (N + 127) / 128;
    int nbComb = (NNODES * 32 + 255) / 256;
    int nbGather = (N * 32 + 255) / 256;

    // 0: composeU (padded 800 rows, qhconst folded in)
    k_composeU<<<800, 128>>>(Wk, bk, Wq, bq, time_b, Muh, Mul, du);
    // 1: fused prep (comb + q gather/split + mask probe)
    k_prep<<<nbComb + nbGather + 1, 256>>>(idx, node_feat, memory, comb,
                                           qh, ql, (const unsigned char*)mask,
                                           N, nbComb, nbGather);
    // 2: u = Mu @ q + du  -> g_u (N x 800, padded)
    mma_gemm<0><<<dim3(mtiles, 7), 256, SMEM_GEMM>>>(
        qh, ql, 128, nullptr, nullptr, 0, 1000,
        Muh, Mul, 128, 4, 800,
        du, nullptr, nullptr, u, 800, nullptr, nullptr, N);
    // 3: fused edge kernel -> mixed hi/lo (N x 768)   [ncu profiles this slot]
    k_edge<<<N, 256>>>(neighbors, t, e_t, e_id, mask, comb,
                       event_feat, time_w, time_b, u, mh, ml, flags, N);
    // 4..6: compose final weights
    k_composeP<<<128, 256>>>(W1, Wo, bv, bo, Pt, cvec);
    k_composeC<<<896, 128>>>(Pt, Wv, W1, Bfh, Bfl);
    k_splitW2<<<64, 256>>>(W2, W2h, W2l);
    // 7: h1 = relu(Bf @ [mixed, q] + b1 + gated cvec) -> h1 hi/lo (N x 128)
    mma_gemm<1><<<dim3(mtiles, 1), 256, SMEM_GEMM>>>(
        mh, ml, 768, qh, ql, 128, 24,
        Bfh, Bfl, 896, 28, 128,
        b1, cvec, flags, nullptr, 0, h1h, h1l, N);
    // 8: out = h1 @ W2^T + b2 -> d_out (N x 128)
    mma_gemm<2><<<dim3(mtiles, 1), 256, SMEM_GEMM>>>(
        h1h, h1l, 128, nullptr, nullptr, 0, 1000,
        W2h, W2l, 128, 4, 128,
        b2, nullptr, nullptr, out, 128, nullptr, nullptr, N);
}

// round 16
// speedup vs baseline: 1.0383x; 1.0383x over previous
#include <cuda_runtime.h>
#include <cuda_bf16.h>
#include <cuda_fp16.h>
#include <math.h>
#include <stdint.h>

#define NN    100000
#define KNB   20
#define DKF   384
#define UPAD  400     // padded per-head u stride (float4-aligned)
#define NNODES 200000

// ================= device scratch =================
__device__ float g_comb[(size_t)NNODES * 128];   // node_feat + memory (precomputed)
__device__ float g_u[(size_t)NN * 800];          // u padded: [h0 c0..384 pad][h1 c0..384 pad]
__device__ uint4 g_qh[(size_t)NN * 16];          // q hi  (N x 128 bf16)   [gemm1 A2]
__device__ uint4 g_ql[(size_t)NN * 16];          // q lo
__device__ uint4 g_qfh[(size_t)NN * 16];         // q hi  (N x 128 fp16)   [gemm0 A]
__device__ uint4 g_qfl[(size_t)NN * 16];         // q lo  fp16
__device__ uint4 g_mh[(size_t)NN * 96];          // mixed hi (N x 768 bf16)
__device__ uint4 g_ml[(size_t)NN * 96];          // mixed lo
__device__ uint4 g_h1h[(size_t)NN * 16];         // h1 hi (N x 128 bf16)
__device__ uint4 g_h1l[(size_t)NN * 16];         // h1 lo
__device__ uint4 g_Muh[14336], g_Mul[14336];     // Mu 800 x 128 fp16 hi/lo
__device__ uint4 g_Bfh[14336], g_Bfl[14336];     // Bf 128 x 896 bf16
__device__ uint4 g_W2h[2048], g_W2l[2048];       // W2 128 x 128 bf16
__device__ float g_du[896];
__device__ float g_Pt[256 * 128];
__device__ float g_cvec[128];
__device__ unsigned char g_flags[NN];
__device__ int   g_mask_is_byte;

// ================= PTX helpers (baseline features only) =================
__device__ __forceinline__ uint32_t smem_u32(const void* p) {
    uint32_t r;
    asm("{ .reg .u64 t; cvta.to.shared.u64 t, %1; cvt.u32.u64 %0, t; }" : "=r"(r) : "l"(p));
    return r;
}
__device__ __forceinline__ void ldm_x4(uint32_t* r, uint32_t addr) {
    asm volatile("ldmatrix.sync.aligned.m8n8.x4.shared.b16 {%0,%1,%2,%3}, [%4];"
                 : "=r"(r[0]), "=r"(r[1]), "=r"(r[2]), "=r"(r[3]) : "r"(addr));
}
__device__ __forceinline__ void ldm_x2(uint32_t* r, uint32_t addr) {
    asm volatile("ldmatrix.sync.aligned.m8n8.x2.shared.b16 {%0,%1}, [%2];"
                 : "=r"(r[0]), "=r"(r[1]) : "r"(addr));
}
__device__ __forceinline__ void mma16816(float* c, const uint32_t* a, const uint32_t* b) {
    asm volatile("mma.sync.aligned.m16n8k16.row.col.f32.bf16.bf16.f32 "
        "{%0,%1,%2,%3}, {%4,%5,%6,%7}, {%8,%9}, {%0,%1,%2,%3};"
        : "+f"(c[0]), "+f"(c[1]), "+f"(c[2]), "+f"(c[3])
        : "r"(a[0]), "r"(a[1]), "r"(a[2]), "r"(a[3]), "r"(b[0]), "r"(b[1]));
}
__device__ __forceinline__ void mma16816h(float* c, const uint32_t* a, const uint32_t* b) {
    asm volatile("mma.sync.aligned.m16n8k16.row.col.f32.f16.f16.f32 "
        "{%0,%1,%2,%3}, {%4,%5,%6,%7}, {%8,%9}, {%0,%1,%2,%3};"
        : "+f"(c[0]), "+f"(c[1]), "+f"(c[2]), "+f"(c[3])
        : "r"(a[0]), "r"(a[1]), "r"(a[2]), "r"(a[3]), "r"(b[0]), "r"(b[1]));
}
__device__ __forceinline__ void cpasync16(uint32_t dst, const void* src, uint32_t srcsize) {
    asm volatile("cp.async.cg.shared.global [%0], [%1], 16, %2;"
                 :: "r"(dst), "l"(src), "r"(srcsize));
}
__device__ __forceinline__ void cpasync16(uint32_t dst, const void* src) {
    asm volatile("cp.async.cg.shared.global [%0], [%1], 16;" :: "r"(dst), "l"(src));
}
__device__ __forceinline__ int mget(const void* m, int i, int isbyte) {
    return isbyte ? (((const unsigned char*)m)[i] != 0) : (((const int*)m)[i] != 0);
}

// ================= setup / compose =================
__device__ __forceinline__ void split_store(__nv_bfloat16* ph, __nv_bfloat16* pl, size_t i, float v) {
    __nv_bfloat16 h = __float2bfloat16(v);
    ph[i] = h;
    pl[i] = __float2bfloat16(v - __bfloat162float(h));
}
__device__ __forceinline__ void split_store_h(__half* ph, __half* pl, size_t i, float v) {
    __half h = __float2half(v);
    ph[i] = h;
    pl[i] = __float2half(v - __half2float(h));
}

// composeU: Mu + du with qhconst folded in; PADDED rows (800 = 2 x 400). fp16 out.
__global__ void k_composeU(const float* __restrict__ Wk, const float* __restrict__ bk,
                           const float* __restrict__ Wq, const float* __restrict__ bq,
                           const float* __restrict__ time_b,
                           __half* __restrict__ Mh, __half* __restrict__ Ml,
                           float* __restrict__ du)
{
    int hc = blockIdx.x;          // 0..799
    int h = hc / UPAD, c = hc % UPAD;
    int e = threadIdx.x;          // 0..127
    __shared__ float krow[128];
    __shared__ float cb[128];
    __shared__ float red[128];
    cb[e] = cosf(time_b[e]);
    krow[e] = (c < 384) ? Wk[(size_t)(h * 128 + e) * 384 + c]
            : ((c == 384) ? bk[h * 128 + e] : 0.f);
    __syncthreads();
    float acc1 = 0.f, acc2 = 0.f;
    #pragma unroll 4
    for (int d = 0; d < 128; d++) {
        const float* row = Wq + (size_t)(h * 128 + d) * 256;
        float kd = krow[d];
        acc1 += kd * row[e];
        acc2 += kd * row[128 + e];
    }
    split_store_h(Mh, Ml, (size_t)hc * 128 + e, acc1);
    red[e] = acc2 * cb[e] + krow[e] * bq[h * 128 + e];
    __syncthreads();
    for (int off = 64; off; off >>= 1) {
        if (e < off) red[e] += red[e + off];
        __syncthreads();
    }
    if (e == 0) du[hc] = red[0];
}

// k_prep: comb + q gather/split (bf16 AND fp16) + mask probe, one launch.
__global__ void k_prep(const int* __restrict__ idx,
                       const float* __restrict__ nf, const float* __restrict__ mem,
                       float* __restrict__ comb,
                       __nv_bfloat16* __restrict__ qh, __nv_bfloat16* __restrict__ ql,
                       __half* __restrict__ qfh, __half* __restrict__ qfl,
                       const unsigned char* __restrict__ mask,
                       int n, int nbComb, int nbGather)
{
    int b = blockIdx.x;
    if (b < nbComb) {
        size_t i = (size_t)b * 256 + threadIdx.x;
        if (i < (size_t)NNODES * 32) {
            float4 a = ((const float4*)nf)[i];
            float4 m = ((const float4*)mem)[i];
            ((float4*)comb)[i] = make_float4(a.x + m.x, a.y + m.y, a.z + m.z, a.w + m.w);
        }
    } else if (b < nbComb + nbGather) {
        int i = (b - nbComb) * 256 + threadIdx.x;
        if (i < n * 32) {
            int node = i >> 5, c4 = i & 31;
            int src = idx[node];
            float4 a = ((const float4*)nf)[(size_t)src * 32 + c4];
            float4 m = ((const float4*)mem)[(size_t)src * 32 + c4];
            float v[4] = { a.x + m.x, a.y + m.y, a.z + m.z, a.w + m.w };
            size_t base = (size_t)i * 4;
            #pragma unroll
            for (int j = 0; j < 4; j++) {
                split_store(qh, ql, base + j, v[j]);
                split_store_h(qfh, qfl, base + j, v[j]);
            }
        }
    } else {
        int any = 0;
        for (int i = threadIdx.x; i < 8192; i += 256)
            if ((i & 3) != 0 && mask[i] != 0) any = 1;
        int r = __syncthreads_or(any);
        if (threadIdx.x == 0) g_mask_is_byte = r ? 1 : 0;
    }
}

__global__ void k_composeP(const float* __restrict__ W1, const float* __restrict__ Wo,
                           const float* __restrict__ bv, const float* __restrict__ bo,
                           float* __restrict__ Pt, float* __restrict__ cvec)
{
    int r = blockIdx.x;           // 0..127
    int a = threadIdx.x;          // 0..255
    __shared__ float w1row[256];
    __shared__ float red[256];
    w1row[a] = W1[(size_t)r * 384 + a];
    __syncthreads();
    float acc = 0.f;
    #pragma unroll 8
    for (int s = 0; s < 256; s++) acc += w1row[s] * Wo[(size_t)s * 256 + a];
    Pt[(size_t)a * 128 + r] = acc;
    red[a] = acc * bv[a] + w1row[a] * bo[a];
    __syncthreads();
    for (int off = 128; off; off >>= 1) {
        if (a < off) red[a] += red[a + off];
        __syncthreads();
    }
    if (a == 0) cvec[r] = red[0];
}

__global__ void k_composeC(const float* __restrict__ Pt, const float* __restrict__ Wv,
                           const float* __restrict__ W1,
                           __nv_bfloat16* __restrict__ Bh, __nv_bfloat16* __restrict__ Bl)
{
    int j = blockIdx.x;           // 0..895
    int r = threadIdx.x;          // 0..127
    if (j >= 768) {
        split_store(Bh, Bl, (size_t)r * 896 + j, W1[(size_t)r * 384 + 256 + (j - 768)]);
        return;
    }
    int h = j / 384, c = j % 384;
    __shared__ float wvcol[128];
    wvcol[r] = Wv[(size_t)(h * 128 + r) * 384 + c];
    __syncthreads();
    float acc = 0.f;
    #pragma unroll 8
    for (int d = 0; d < 128; d++)
        acc += Pt[(size_t)(h * 128 + d) * 128 + r] * wvcol[d];
    split_store(Bh, Bl, (size_t)r * 896 + j, acc);
}

__global__ void k_splitW2(const float* __restrict__ W2,
                          __nv_bfloat16* __restrict__ wh, __nv_bfloat16* __restrict__ wl)
{
    int i = blockIdx.x * 256 + threadIdx.x;
    if (i < 128 * 128) split_store(wh, wl, i, W2[i]);
}

// ================= HMMA GEMM (cp.async double-buffered, 2 CTAs/SM) ===========
// MODE 0: bf16 3-term.  MODE 1: fp16 2-term (D = Ah*Bh + Al*Bh), grid axes
// swapped (x = r-tiles, y = m-tiles) so A-tiles are L2-reused across r-tiles.
#define LDS_STRIDE 40                 // 16-bit elems; 80B rows, ldmatrix conflict-free
#define TILE_B     (128 * LDS_STRIDE * 2)   // 10240 bytes per tile
#define STAGE_B    (4 * TILE_B)             // AsH AsL BsH BsL
#define SMEM_GEMM  (2 * STAGE_B)            // 81920

template<int EPI, int MODE>
__global__ __launch_bounds__(256, 2)
void mma_gemm(const __nv_bfloat16* __restrict__ Ah, const __nv_bfloat16* __restrict__ Al, int lda,
              const __nv_bfloat16* __restrict__ A2h, const __nv_bfloat16* __restrict__ A2l, int lda2, int ksplit,
              const __nv_bfloat16* __restrict__ Bh, const __nv_bfloat16* __restrict__ Bl, int ldb,
              int ktiles, int Rtot,
              const float* __restrict__ bias, const float* __restrict__ bias2,
              const unsigned char* __restrict__ flags,
              float* __restrict__ OutF, int ldc,
              __nv_bfloat16* __restrict__ OutH, __nv_bfloat16* __restrict__ OutL, int Ntot)
{
    extern __shared__ char dsm[];
    const uint32_t sb = smem_u32(dsm);

    const int tid = threadIdx.x;
    const int lane = tid & 31, wid = tid >> 5;
    const int wm = wid >> 2, wn = wid & 3;      // 2 x 4 warp grid
    const int m0 = (MODE == 1 ? blockIdx.y : blockIdx.x) * 128;
    const int r0 = (MODE == 1 ? blockIdx.x : blockIdx.y) * 128;

    int vrows = Ntot - m0;
    if (vrows > 128) vrows = 128;
    if (vrows < 0) vrows = 0;

    float acc[4][4][4];
    #pragma unroll
    for (int a = 0; a < 4; a++)
        #pragma unroll
        for (int b = 0; b < 4; b++)
            #pragma unroll
            for (int c = 0; c < 4; c++) acc[a][b][c] = 0.f;

    const int lrow = tid >> 2;                 // 0..63 (+64 on 2nd pass)
    const int lc8 = (tid & 3) * 8;             // elem col within 32

    auto issue_stage = [&](int kt) {
        uint32_t base = sb + (kt & 1) * STAGE_B;
        const __nv_bfloat16 *sh, *sl; int st, k0;
        if (kt < ksplit) { sh = Ah;  sl = Al;  st = lda;  k0 = kt * 32; }
        else             { sh = A2h; sl = A2l; st = lda2; k0 = (kt - ksplit) * 32; }
        #pragma unroll
        for (int i = 0; i < 2; i++) {
            int row = lrow + i * 64;
            int srow = (row < vrows) ? row : 0;
            uint32_t sz = (row < vrows) ? 16u : 0u;
            uint32_t doff = row * (LDS_STRIDE * 2) + lc8 * 2;
            cpasync16(base + doff,
                      sh + (size_t)(m0 + srow) * st + k0 + lc8, sz);
            cpasync16(base + TILE_B + doff,
                      sl + (size_t)(m0 + srow) * st + k0 + lc8, sz);
            cpasync16(base + 2 * TILE_B + doff,
                      Bh + (size_t)(r0 + row) * ldb + kt * 32 + lc8);
            if (MODE == 0)
                cpasync16(base + 3 * TILE_B + doff,
                          Bl + (size_t)(r0 + row) * ldb + kt * 32 + lc8);
        }
        asm volatile("cp.async.commit_group;" ::: "memory");
    };

    const int arow = wm * 64 + (lane & 15);
    const int acolsel = ((lane >> 4) & 1) * 8;
    const int l16 = lane & 15;
    const int brow = wn * 32 + (l16 & 7);
    const int bcolsel = ((l16 >> 3) & 1) * 8;

    issue_stage(0);

    for (int kt = 0; kt < ktiles; kt++) {
        if (kt + 1 < ktiles) {
            issue_stage(kt + 1);
            asm volatile("cp.async.wait_group 1;" ::: "memory");
        } else {
            asm volatile("cp.async.wait_group 0;" ::: "memory");
        }
        __syncthreads();

        const uint32_t cb = sb + (kt & 1) * STAGE_B;
        const uint32_t sAH = cb, sAL = cb + TILE_B;
        const uint32_t sBH = cb + 2 * TILE_B, sBL = cb + 3 * TILE_B;

        #pragma unroll
        for (int ks = 0; ks < 2; ks++) {
            const int acol = ks * 16 + acolsel;
            const int bcol = ks * 16 + bcolsel;
            uint32_t af[4][4], bhf[4][2], blf[4][2];
            #pragma unroll
            for (int mi = 0; mi < 4; mi++)
                ldm_x4(af[mi], sAH + (uint32_t)(((arow + mi * 16) * LDS_STRIDE + acol) * 2));
            #pragma unroll
            for (int ni = 0; ni < 4; ni++) {
                ldm_x2(bhf[ni], sBH + (uint32_t)(((brow + ni * 8) * LDS_STRIDE + bcol) * 2));
                if (MODE == 0)
                    ldm_x2(blf[ni], sBL + (uint32_t)(((brow + ni * 8) * LDS_STRIDE + bcol) * 2));
            }
            #pragma unroll
            for (int mi = 0; mi < 4; mi++)
                #pragma unroll
                for (int ni = 0; ni < 4; ni++) {
                    if (MODE == 0) {
                        mma16816(acc[mi][ni], af[mi], bhf[ni]);    // Ah*Bh
                        mma16816(acc[mi][ni], af[mi], blf[ni]);    // Ah*Bl
                    } else {
                        mma16816h(acc[mi][ni], af[mi], bhf[ni]);   // Ah*Bh (fp16)
                    }
                }
            #pragma unroll
            for (int mi = 0; mi < 4; mi++)
                ldm_x4(af[mi], sAL + (uint32_t)(((arow + mi * 16) * LDS_STRIDE + acol) * 2));
            #pragma unroll
            for (int mi = 0; mi < 4; mi++)
                #pragma unroll
                for (int ni = 0; ni < 4; ni++) {
                    if (MODE == 0) mma16816(acc[mi][ni], af[mi], bhf[ni]);    // Al*Bh
                    else           mma16816h(acc[mi][ni], af[mi], bhf[ni]);   // Al*Bh (fp16)
                }
        }
        __syncthreads();
    }

    // ---- epilogue ----
    #pragma unroll
    for (int mi = 0; mi < 4; mi++) {
        int nrow0 = m0 + wm * 64 + mi * 16 + (lane >> 2);
        #pragma unroll
        for (int half = 0; half < 2; half++) {
            int n = nrow0 + half * 8;
            if (n >= Ntot) continue;
            bool fl = false;
            if (EPI == 1) fl = (flags[n] != 0);
            #pragma unroll
            for (int ni = 0; ni < 4; ni++) {
                int r = r0 + wn * 32 + ni * 8 + (lane & 3) * 2;
                float v0 = acc[mi][ni][half * 2 + 0];
                float v1 = acc[mi][ni][half * 2 + 1];
                if (EPI == 0) {
                    if (r < Rtot)     OutF[(size_t)n * ldc + r]     = v0 + bias[r];
                    if (r + 1 < Rtot) OutF[(size_t)n * ldc + r + 1] = v1 + bias[r + 1];
                } else if (EPI == 1) {
                    v0 += bias[r]     + (fl ? 0.f : bias2[r]);
                    v1 += bias[r + 1] + (fl ? 0.f : bias2[r + 1]);
                    v0 = fmaxf(v0, 0.f);
                    v1 = fmaxf(v1, 0.f);
                    __nv_bfloat16 h0 = __float2bfloat16(v0), h1 = __float2bfloat16(v1);
                    *(__nv_bfloat162*)(OutH + (size_t)n * 128 + r) = __halves2bfloat162(h0, h1);
                    __nv_bfloat16 l0 = __float2bfloat16(v0 - __bfloat162float(h0));
                    __nv_bfloat16 l1 = __float2bfloat16(v1 - __bfloat162float(h1));
                    *(__nv_bfloat162*)(OutL + (size_t)n * 128 + r) = __halves2bfloat162(l0, l1);
                } else {
                    OutF[(size_t)n * ldc + r]     = v0 + bias[r];
                    OutF[(size_t)n * ldc + r + 1] = v1 + bias[r + 1];
                }
            }
        }
    }
}

// ================= fused per-node edge kernel (R12 version, reverted) ========
__global__ __launch_bounds__(256)
void k_edge(const int* __restrict__ neighbors, const float* __restrict__ t,
            const float* __restrict__ e_t, const int* __restrict__ e_id,
            const void* __restrict__ mask,
            const float* __restrict__ comb,
            const float* __restrict__ event_feat,
            const float* __restrict__ time_w, const float* __restrict__ time_b,
            const float* __restrict__ u,
            __nv_bfloat16* __restrict__ mixh, __nv_bfloat16* __restrict__ mixl,
            unsigned char* __restrict__ flags, int Ntot)
{
    int n = blockIdx.x;
    if (n >= Ntot) return;
    int tid = threadIdx.x;
    int lane = tid & 31, warp = tid >> 5;
    const int isb = g_mask_is_byte;

    __shared__ float kvc[KNB][DKF];
    __shared__ float tw[128], tb[128];
    __shared__ float attn[2][KNB];
    __shared__ float sc[2][KNB];
    __shared__ int s_nb[KNB], s_eid[KNB], s_mk[KNB];
    __shared__ float s_dt[KNB];
    __shared__ int s_nonb;

    // u -> regs for score warps 0-3 (issued first; independent of everything)
    const float* ubase = u + (size_t)n * 800;
    float4 u0[3], u1[3];
    float ub0 = 0.f, ub1 = 0.f;
    if (warp < 4) {
        #pragma unroll
        for (int i = 0; i < 3; i++) {
            u0[i] = *(const float4*)(ubase + lane * 4 + 128 * i);
            u1[i] = *(const float4*)(ubase + UPAD + lane * 4 + 128 * i);
        }
        ub0 = ubase[384]; ub1 = ubase[UPAD + 384];
    }

    if (tid >= 128) { tw[tid - 128] = time_w[tid - 128]; tb[tid - 128] = time_b[tid - 128]; }
    if (tid < KNB) {
        s_nb[tid]  = neighbors[n * KNB + tid];
        s_eid[tid] = e_id[n * KNB + tid];
        s_mk[tid]  = mget(mask, n * KNB + tid, isb);
        s_dt[tid]  = t[n] - e_t[n * KNB + tid];
    }
    __syncthreads();
    if (tid == 0) {
        int any = 0;
        #pragma unroll
        for (int k = 0; k < KNB; k++) any |= s_mk[k];
        s_nonb = !any;
    }
    __syncthreads();
    const int nonb = s_nonb;
    const uint32_t kvb = smem_u32(kvc);

    // phase B: all gathers as cp.async (zero-fill when gated off)
    for (int i = tid; i < 640; i += 256) {
        int k = i >> 5, c4 = i & 31;
        int mk = s_mk[k];
        cpasync16(kvb + (uint32_t)(k * DKF + c4 * 4) * 4,
                  comb + (size_t)s_nb[k] * 128 + c4 * 4, mk ? 16u : 0u);
        cpasync16(kvb + (uint32_t)(k * DKF + 256 + c4 * 4) * 4,
                  event_feat + (size_t)s_eid[k] * 128 + c4 * 4, (mk | nonb) ? 16u : 0u);
    }
    asm volatile("cp.async.commit_group;" ::: "memory");

    // phase C: time encode while gathers are in flight
    for (int i = tid; i < 640; i += 256) {
        int k = i >> 5, c4 = i & 31;
        float4 v = make_float4(0.f, 0.f, 0.f, 0.f);
        if (s_mk[k] | nonb) {
            float dt = s_dt[k];
            int j = c4 * 4;
            v.x = __cosf(__fadd_rn(__fmul_rn(dt, tw[j + 0]), tb[j + 0]));
            v.y = __cosf(__fadd_rn(__fmul_rn(dt, tw[j + 1]), tb[j + 1]));
            v.z = __cosf(__fadd_rn(__fmul_rn(dt, tw[j + 2]), tb[j + 2]));
            v.w = __cosf(__fadd_rn(__fmul_rn(dt, tw[j + 3]), tb[j + 3]));
        }
        *(float4*)&kvc[k][128 + c4 * 4] = v;
    }
    asm volatile("cp.async.wait_group 0;" ::: "memory");
    __syncthreads();

    // scores: 4 warps, 5 k-slots each; one kvc float4 read feeds BOTH heads
    if (warp < 4) {
        for (int k = warp; k < KNB; k += 4) {
            if (!(s_mk[k] | nonb)) continue;      // warp-uniform
            float a0 = 0.f, a1 = 0.f;
            #pragma unroll
            for (int i = 0; i < 3; i++) {
                float4 v = *(const float4*)&kvc[k][lane * 4 + 128 * i];
                a0 += u0[i].x * v.x + u0[i].y * v.y + u0[i].z * v.z + u0[i].w * v.w;
                a1 += u1[i].x * v.x + u1[i].y * v.y + u1[i].z * v.z + u1[i].w * v.w;
            }
            #pragma unroll
            for (int off = 16; off; off >>= 1) {
                a0 += __shfl_down_sync(0xffffffffu, a0, off);
                a1 += __shfl_down_sync(0xffffffffu, a1, off);
            }
            if (lane == 0) {
                sc[0][k] = (a0 + ub0) * 0.08838834764831845f;
                sc[1][k] = (a1 + ub1) * 0.08838834764831845f;
            }
        }
    }
    __syncthreads();

    // masked softmax per head (warps 0,1)
    if (warp < 2) {
        int h = warp;
        int valid = 0;
        float s = -INFINITY;
        if (lane < KNB) {
            valid = s_mk[lane] | nonb;
            if (valid) s = sc[h][lane];
        }
        float m = s;
        #pragma unroll
        for (int off = 16; off; off >>= 1) m = fmaxf(m, __shfl_xor_sync(0xffffffffu, m, off));
        float e = (lane < KNB && valid) ? __expf(s - m) : 0.f;
        float sum = e;
        #pragma unroll
        for (int off = 16; off; off >>= 1) sum += __shfl_xor_sync(0xffffffffu, sum, off);
        if (lane < KNB) attn[h][lane] = e / sum;
    }
    __syncthreads();

    // mix: one float2 kvc read feeds BOTH heads (threads 0..191, 2 cols each)
    float gate = nonb ? 0.f : 1.f;
    if (tid < 192) {
        int j = tid * 2;
        float a00 = 0.f, a01 = 0.f, a10 = 0.f, a11 = 0.f;
        #pragma unroll
        for (int k = 0; k < KNB; k++) {
            float2 v = *(const float2*)&kvc[k][j];
            float w0 = attn[0][k], w1 = attn[1][k];
            a00 += w0 * v.x; a01 += w0 * v.y;
            a10 += w1 * v.x; a11 += w1 * v.y;
        }
        a00 *= gate; a01 *= gate; a10 *= gate; a11 *= gate;
        __nv_bfloat16 h00 = __float2bfloat16(a00), h01 = __float2bfloat16(a01);
        __nv_bfloat16 h10 = __float2bfloat16(a10), h11 = __float2bfloat16(a11);
        *(__nv_bfloat162*)(mixh + (size_t)n * 768 + j)       = __halves2bfloat162(h00, h01);
        *(__nv_bfloat162*)(mixh + (size_t)n * 768 + 384 + j) = __halves2bfloat162(h10, h11);
        __nv_bfloat16 l00 = __float2bfloat16(a00 - __bfloat162float(h00));
        __nv_bfloat16 l01 = __float2bfloat16(a01 - __bfloat162float(h01));
        __nv_bfloat16 l10 = __float2bfloat16(a10 - __bfloat162float(h10));
        __nv_bfloat16 l11 = __float2bfloat16(a11 - __bfloat162float(h11));
        *(__nv_bfloat162*)(mixl + (size_t)n * 768 + j)       = __halves2bfloat162(l00, l01);
        *(__nv_bfloat162*)(mixl + (size_t)n * 768 + 384 + j) = __halves2bfloat162(l10, l11);
    }
    if (tid == 0) flags[n] = (unsigned char)nonb;
}

// ================= launch =================
extern "C" void kernel_launch(void* const* d_in, const int* in_sizes, int n_in,
                              void* d_out, int out_size)
{
    const int*   idx        = (const int*)d_in[0];
    const float* t          = (const float*)d_in[1];
    const int*   neighbors  = (const int*)d_in[2];
    const float* e_t        = (const float*)d_in[3];
    const int*   e_id       = (const int*)d_in[4];
    const void*  mask       = d_in[5];
    const float* node_feat  = (const float*)d_in[6];
    const float* memory     = (const float*)d_in[7];
    const float* event_feat = (const float*)d_in[8];
    const float* time_w     = (const float*)d_in[9];
    const float* time_b     = (const float*)d_in[10];
    const float* Wq = (const float*)d_in[11];
    const float* bq = (const float*)d_in[12];
    const float* Wk = (const float*)d_in[13];
    const float* bk = (const float*)d_in[14];
    const float* Wv = (const float*)d_in[15];
    const float* bv = (const float*)d_in[16];
    const float* Wo = (const float*)d_in[17];
    const float* bo = (const float*)d_in[18];
    const float* W1 = (const float*)d_in[19];
    const float* b1 = (const float*)d_in[20];
    const float* W2 = (const float*)d_in[21];
    const float* b2 = (const float*)d_in[22];
    float* out = (float*)d_out;

    int N = in_sizes[0];
    if (N > NN) N = NN;

    float *u, *du, *Pt, *cvec, *comb;
    __nv_bfloat16 *qh, *ql, *mh, *ml, *h1h, *h1l, *Bfh, *Bfl, *W2h, *W2l;
    __half *qfh, *qfl, *Muh, *Mul;
    unsigned char* flags;
    cudaGetSymbolAddress((void**)&u, g_u);
    cudaGetSymbolAddress((void**)&du, g_du);
    cudaGetSymbolAddress((void**)&Pt, g_Pt);
    cudaGetSymbolAddress((void**)&cvec, g_cvec);
    cudaGetSymbolAddress((void**)&comb, g_comb);
    cudaGetSymbolAddress((void**)&qh, g_qh);
    cudaGetSymbolAddress((void**)&ql, g_ql);
    cudaGetSymbolAddress((void**)&qfh, g_qfh);
    cudaGetSymbolAddress((void**)&qfl, g_qfl);
    cudaGetSymbolAddress((void**)&mh, g_mh);
    cudaGetSymbolAddress((void**)&ml, g_ml);
    cudaGetSymbolAddress((void**)&h1h, g_h1h);
    cudaGetSymbolAddress((void**)&h1l, g_h1l);
    cudaGetSymbolAddress((void**)&Muh, g_Muh);
    cudaGetSymbolAddress((void**)&Mul, g_Mul);
    cudaGetSymbolAddress((void**)&Bfh, g_Bfh);
    cudaGetSymbolAddress((void**)&Bfl, g_Bfl);
    cudaGetSymbolAddress((void**)&W2h, g_W2h);
    cudaGetSymbolAddress((void**)&W2l, g_W2l);
    cudaGetSymbolAddress((void**)&flags, g_flags);

    cudaFuncSetAttribute(mma_gemm<0, 1>, cudaFuncAttributeMaxDynamicSharedMemorySize, SMEM_GEMM);
    cudaFuncSetAttribute(mma_gemm<1, 0>, cudaFuncAttributeMaxDynamicSharedMemorySize, SMEM_GEMM);
    cudaFuncSetAttribute(mma_gemm<2, 0>, cudaFuncAttributeMaxDynamicSharedMemorySize, SMEM_GEMM);

    int mtiles = (N + 127) / 128;
    int nbComb = (NNODES * 32 + 255) / 256;
    int nbGather = (N * 32 + 255) / 256;

    // 0: composeU (padded 800 rows, qhconst folded in, fp16 out)
    k_composeU<<<800, 128>>>(Wk, bk, Wq, bq, time_b, Muh, Mul, du);
    // 1: fused prep (comb + q gather/split bf16+fp16 + mask probe)
    k_prep<<<nbComb + nbGather + 1, 256>>>(idx, node_feat, memory, comb,
                                           qh, ql, qfh, qfl,
                                           (const unsigned char*)mask,
                                           N, nbComb, nbGather);
    // 2: u = Mu @ q + du  (fp16 2-term, grid swapped: x=r-tiles, y=m-tiles)
    mma_gemm<0, 1><<<dim3(7, mtiles), 256, SMEM_GEMM>>>(
        (const __nv_bfloat16*)qfh, (const __nv_bfloat16*)qfl, 128,
        nullptr, nullptr, 0, 1000,
        (const __nv_bfloat16*)Muh, (const __nv_bfloat16*)Mul, 128, 4, 800,
        du, nullptr, nullptr, u, 800, nullptr, nullptr, N);
    // 3: fused edge kernel -> mixed hi/lo (N x 768)   [ncu profiles this slot]
    k_edge<<<N, 256>>>(neighbors, t, e_t, e_id, mask, comb,
                       event_feat, time_w, time_b, u, mh, ml, flags, N);
    // 4..6: compose final weights
    k_composeP<<<128, 256>>>(W1, Wo, bv, bo, Pt, cvec);
    k_composeC<<<896, 128>>>(Pt, Wv, W1, Bfh, Bfl);
    k_splitW2<<<64, 256>>>(W2, W2h, W2l);
    // 7: h1 = relu(Bf @ [mixed, q] + b1 + gated cvec) -> h1 hi/lo (N x 128)
    mma_gemm<1, 0><<<dim3(mtiles, 1), 256, SMEM_GEMM>>>(
        mh, ml, 768, qh, ql, 128, 24,
        Bfh, Bfl, 896, 28, 128,
        b1, cvec, flags, nullptr, 0, h1h, h1l, N);
    // 8: out = h1 @ W2^T + b2 -> d_out (N x 128)
    mma_gemm<2, 0><<<dim3(mtiles, 1), 256, SMEM_GEMM>>>(
        h1h, h1l, 128, nullptr, nullptr, 0, 1000,
        W2h, W2l, 128, 4, 128,
        b2, nullptr, nullptr, out, 128, nullptr, nullptr, N);
}